// round 1
// baseline (speedup 1.0000x reference)
#include <cuda_runtime.h>
#include <math.h>

#define NN 50000
#define EE 1600000
#define DD 128
#define ET (EE + NN)

// ---------------- scratch (static device globals; no allocation) ------------
__device__ float g_bufA[NN * DD];   // layer input (expmap0(x), then activations)
__device__ float g_bufH[NN * DD];   // h = A @ W
__device__ float g_s[NN];           // h . a_src
__device__ float g_d[NN];           // h . a_dst
__device__ int   g_count[NN];
__device__ int   g_rowptr[NN + 1];
__device__ int   g_cursor[NN];
__device__ int   g_col[ET];         // CSR (by dst) source indices

// ---------------- CSR build --------------------------------------------------
__global__ void init_count_kernel() {
    int i = blockIdx.x * blockDim.x + threadIdx.x;
    if (i < NN) g_count[i] = 1;   // self loop contributes 1 to every node
}

__global__ void hist_kernel(const int* __restrict__ dst) {
    int i = blockIdx.x * blockDim.x + threadIdx.x;
    if (i < EE) atomicAdd(&g_count[dst[i]], 1);
}

// single-block exclusive scan over g_count -> g_rowptr, g_cursor
__global__ void scan_kernel() {
    __shared__ int wsum[32];
    __shared__ int off;
    int tid = threadIdx.x, lane = tid & 31, wid = tid >> 5;
    if (tid == 0) off = 0;
    __syncthreads();
    for (int base = 0; base < NN; base += 1024) {
        int i = base + tid;
        int v = (i < NN) ? g_count[i] : 0;
        int x = v;
        #pragma unroll
        for (int o = 1; o < 32; o <<= 1) {
            int y = __shfl_up_sync(0xffffffffu, x, o);
            if (lane >= o) x += y;
        }
        if (lane == 31) wsum[wid] = x;
        __syncthreads();
        if (wid == 0) {
            int w = wsum[lane];
            int xx = w;
            #pragma unroll
            for (int o = 1; o < 32; o <<= 1) {
                int y = __shfl_up_sync(0xffffffffu, xx, o);
                if (lane >= o) xx += y;
            }
            wsum[lane] = xx - w;   // exclusive warp offsets
        }
        __syncthreads();
        int incl = x + wsum[wid];
        int excl = incl - v + off;
        if (i < NN) { g_rowptr[i] = excl; g_cursor[i] = excl; }
        __syncthreads();
        if (tid == 1023) off += incl;   // incl of last thread == chunk total
        __syncthreads();
    }
    if (threadIdx.x == 0) g_rowptr[NN] = off;
}

__global__ void scatter_kernel(const int* __restrict__ src, const int* __restrict__ dst) {
    int i = blockIdx.x * blockDim.x + threadIdx.x;
    if (i >= ET) return;
    int s, t;
    if (i < EE) { s = src[i]; t = dst[i]; }
    else        { s = i - EE; t = s; }           // self loops
    int pos = atomicAdd(&g_cursor[t], 1);
    g_col[pos] = s;
}

// ---------------- expmap0 ----------------------------------------------------
__global__ void expmap_kernel(const float* __restrict__ x) {
    int gid = blockIdx.x * blockDim.x + threadIdx.x;
    int row = gid >> 5, lane = gid & 31;
    if (row >= NN) return;
    float4 v = ((const float4*)x)[row * 32 + lane];
    float ss = v.x * v.x + v.y * v.y + v.z * v.z + v.w * v.w;
    #pragma unroll
    for (int o = 16; o; o >>= 1) ss += __shfl_xor_sync(0xffffffffu, ss, o);
    float n = sqrtf(ss);
    n = fmaxf(n, 1e-15f);
    float sc = tanhf(n) / n;
    v.x *= sc; v.y *= sc; v.z *= sc; v.w *= sc;
    ((float4*)g_bufA)[row * 32 + lane] = v;
}

// ---------------- GEMM: H = A @ W, fused s/d epilogue ------------------------
// block: 128 threads, tile 64 rows x 128 cols. W (64KB) + A tile (32KB) in smem.
__global__ void gemm_kernel(const float* __restrict__ A, const float* __restrict__ W,
                            const float* __restrict__ avs, const float* __restrict__ avd) {
    extern __shared__ float sm[];
    float* Ws = sm;              // [128][128]
    float* As = sm + 128 * 128;  // [64][128]
    int tid = threadIdx.x;
    int row0 = blockIdx.x * 64;

    for (int i = tid; i < (128 * 128) / 4; i += 128)
        ((float4*)Ws)[i] = ((const float4*)W)[i];
    for (int i = tid; i < (64 * 128) / 4; i += 128) {
        int r = i >> 5, c4 = i & 31;
        int row = row0 + r;
        float4 v = (row < NN) ? ((const float4*)A)[row * 32 + c4]
                              : make_float4(0.f, 0.f, 0.f, 0.f);
        ((float4*)As)[i] = v;
    }
    __syncthreads();

    int w = tid >> 5, lane = tid & 31;
    int r0 = w * 16;        // 16 rows per warp (all lanes share rows -> smem broadcast)
    int c0 = lane * 4;      // 4 cols per lane

    float acc[16][4];
    #pragma unroll
    for (int i = 0; i < 16; i++)
        #pragma unroll
        for (int j = 0; j < 4; j++) acc[i][j] = 0.f;

    #pragma unroll 4
    for (int k = 0; k < 128; k++) {
        float4 wk = *(const float4*)&Ws[k * 128 + c0];
        #pragma unroll
        for (int i = 0; i < 16; i++) {
            float a = As[(r0 + i) * 128 + k];
            acc[i][0] = fmaf(a, wk.x, acc[i][0]);
            acc[i][1] = fmaf(a, wk.y, acc[i][1]);
            acc[i][2] = fmaf(a, wk.z, acc[i][2]);
            acc[i][3] = fmaf(a, wk.w, acc[i][3]);
        }
    }

    float4 asv = *(const float4*)&avs[c0];
    float4 adv = *(const float4*)&avd[c0];
    #pragma unroll
    for (int i = 0; i < 16; i++) {
        int row = row0 + r0 + i;
        if (row < NN) {   // uniform across warp
            float4 o;
            o.x = acc[i][0]; o.y = acc[i][1]; o.z = acc[i][2]; o.w = acc[i][3];
            ((float4*)g_bufH)[row * 32 + lane] = o;
            float ps = o.x * asv.x + o.y * asv.y + o.z * asv.z + o.w * asv.w;
            float pd = o.x * adv.x + o.y * adv.y + o.z * adv.z + o.w * adv.w;
            #pragma unroll
            for (int off = 16; off; off >>= 1) {
                ps += __shfl_xor_sync(0xffffffffu, ps, off);
                pd += __shfl_xor_sync(0xffffffffu, pd, off);
            }
            if (lane == 0) { g_s[row] = ps; g_d[row] = pd; }
        }
    }
}

// ---------------- per-node attention aggregation (1 warp / node) -------------
__global__ void agg_kernel(const float* __restrict__ H, const float* __restrict__ sarr,
                           const float* __restrict__ darr, const float* __restrict__ bias,
                           float* __restrict__ out, int act) {
    __shared__ float ebuf[8][128];
    int lane = threadIdx.x & 31, ws = threadIdx.x >> 5;
    int node = (blockIdx.x * blockDim.x + threadIdx.x) >> 5;
    if (node >= NN) return;

    int beg = g_rowptr[node], end = g_rowptr[node + 1];
    float di = darr[node];

    // pass 1: online softmax (per lane, then warp combine)
    float m = -1e30f, den = 0.f;
    for (int j = beg + lane; j < end; j += 32) {
        float e = sarr[g_col[j]] + di;
        e = e > 0.f ? e : 0.2f * e;
        float nm = fmaxf(m, e);
        den = den * __expf(m - nm) + __expf(e - nm);
        m = nm;
    }
    #pragma unroll
    for (int o = 16; o; o >>= 1) {
        float m2 = __shfl_xor_sync(0xffffffffu, m, o);
        float d2 = __shfl_xor_sync(0xffffffffu, den, o);
        float nm = fmaxf(m, m2);
        den = den * __expf(m - nm) + d2 * __expf(m2 - nm);
        m = nm;
    }
    float inv = 1.f / den;

    // pass 2: weighted gather-accumulate (alpha staged in smem per warp)
    float4 acc = make_float4(0.f, 0.f, 0.f, 0.f);
    for (int cb = beg; cb < end; cb += 128) {
        int cn = min(128, end - cb);
        for (int j = lane; j < cn; j += 32) {
            float e = sarr[g_col[cb + j]] + di;
            e = e > 0.f ? e : 0.2f * e;
            ebuf[ws][j] = __expf(e - m) * inv;
        }
        __syncwarp();
        for (int j = 0; j < cn; j++) {
            int sn = g_col[cb + j];           // broadcast load
            float al = ebuf[ws][j];
            float4 hv = ((const float4*)H)[sn * 32 + lane];  // L2-resident gather
            acc.x = fmaf(al, hv.x, acc.x);
            acc.y = fmaf(al, hv.y, acc.y);
            acc.z = fmaf(al, hv.z, acc.z);
            acc.w = fmaf(al, hv.w, acc.w);
        }
        __syncwarp();
    }

    float4 bv = ((const float4*)bias)[lane];
    acc.x += bv.x; acc.y += bv.y; acc.z += bv.z; acc.w += bv.w;
    if (act) {
        acc.x = 2.f * tanhf(acc.x);
        acc.y = 2.f * tanhf(acc.y);
        acc.z = 2.f * tanhf(acc.z);
        acc.w = 2.f * tanhf(acc.w);
    }
    ((float4*)out)[node * 32 + lane] = acc;
}

// ---------------- launch ------------------------------------------------------
extern "C" void kernel_launch(void* const* d_in, const int* in_sizes, int n_in,
                              void* d_out, int out_size) {
    const float* x   = (const float*)d_in[0];
    const int*   ei  = (const int*)d_in[1];
    const int*   esrc = ei;
    const int*   edst = ei + EE;
    const float* W1  = (const float*)d_in[2];
    const float* a1s = (const float*)d_in[3];
    const float* a1d = (const float*)d_in[4];
    const float* b1  = (const float*)d_in[5];
    const float* W2  = (const float*)d_in[6];
    const float* a2s = (const float*)d_in[7];
    const float* a2d = (const float*)d_in[8];
    const float* b2  = (const float*)d_in[9];
    const float* W3  = (const float*)d_in[10];
    const float* a3s = (const float*)d_in[11];
    const float* a3d = (const float*)d_in[12];
    const float* b3  = (const float*)d_in[13];
    float* out = (float*)d_out;

    float *pA, *pH, *pS, *pD;
    cudaGetSymbolAddress((void**)&pA, g_bufA);
    cudaGetSymbolAddress((void**)&pH, g_bufH);
    cudaGetSymbolAddress((void**)&pS, g_s);
    cudaGetSymbolAddress((void**)&pD, g_d);

    const int SMEM = (128 * 128 + 64 * 128) * 4;   // 98304 B
    cudaFuncSetAttribute(gemm_kernel, cudaFuncAttributeMaxDynamicSharedMemorySize, SMEM);

    // CSR build (once per launch; graph is the same across the 3 layers)
    init_count_kernel<<<(NN + 255) / 256, 256>>>();
    hist_kernel<<<(EE + 255) / 256, 256>>>(edst);
    scan_kernel<<<1, 1024>>>();
    scatter_kernel<<<(ET + 255) / 256, 256>>>(esrc, edst);

    // expmap0
    expmap_kernel<<<(NN * 32 + 255) / 256, 256>>>(x);

    int gemm_blocks = (NN + 63) / 64;
    int agg_blocks  = (NN + 7) / 8;

    // layer 1
    gemm_kernel<<<gemm_blocks, 128, SMEM>>>(pA, W1, a1s, a1d);
    agg_kernel<<<agg_blocks, 256>>>(pH, pS, pD, b1, pA, 1);
    // layer 2
    gemm_kernel<<<gemm_blocks, 128, SMEM>>>(pA, W2, a2s, a2d);
    agg_kernel<<<agg_blocks, 256>>>(pH, pS, pD, b2, pA, 1);
    // layer 3
    gemm_kernel<<<gemm_blocks, 128, SMEM>>>(pA, W3, a3s, a3d);
    agg_kernel<<<agg_blocks, 256>>>(pH, pS, pD, b3, out, 0);
}